// round 8
// baseline (speedup 1.0000x reference)
#include <cuda_runtime.h>
#include <cstdint>

// Custom_Decoder fused GEMM + overlap_add; cp.async ring, 512-thread blocks,
// two K-halves of each unit consumed in parallel (kh = warp-level bit).
//
// out[bc,16p+r]   = x[2p].wt[r]   + x[2p-1].wt[8+r]
// out[bc,16p+8+r] = x[2p+1].wt[r] + x[2p]  .wt[8+r]
//
// 144 persistent blocks x 7 units; unit = 32 pairs (64 frames) of one bc.
// Stage s = (unit iu, k-half h): slot s%3 = 65 frame-half rows x 1KB.
// Unit iu needs stages 2iu and 2iu+1 resident simultaneously.

#define E_DIM 512
#define HALF  256
#define FRAMES 3999
#define PAIRS 2000
#define OUT_T 32000
#define UNITS_PER_BC 63
#define GRID 144
#define UNITS_PER_BLOCK 7          // 144*7 = 1008 = 16*63
#define NSTAGES (2*UNITS_PER_BLOCK)
#define NTH 512
#define SLOT_BYTES (65*1024)
#define W_BYTES (16*E_DIM*4)       // 32768
#define SMEM_TOTAL (W_BYTES + 3*SLOT_BYTES)   // 232448 = sm_10x optin max
#define CHUNKS 4160                // SLOT_BYTES/16

typedef unsigned long long ull;

__device__ __forceinline__ void ffma2(ull &d, ull a, ull b) {
    asm("fma.rn.f32x2 %0, %1, %2, %0;" : "+l"(d) : "l"(a), "l"(b));
}
__device__ __forceinline__ float flo(ull v){ return __uint_as_float((unsigned)(v & 0xffffffffu)); }
__device__ __forceinline__ float fhi(ull v){ return __uint_as_float((unsigned)(v >> 32)); }

__device__ __forceinline__ void cp16(uint32_t sa, const void* g) {
    asm volatile("cp.async.cg.shared.global [%0], [%1], 16;" :: "r"(sa), "l"(g));
}
__device__ __forceinline__ void cp_commit() { asm volatile("cp.async.commit_group;"); }
__device__ __forceinline__ void cp_wait1()  { asm volatile("cp.async.wait_group 1;"); }

// stage s: unit iu = s/2, k-half h = s&1. Always commits (empty groups past
// the end keep wait_group(1) bookkeeping uniform).
__device__ __forceinline__ void issue_stage(char* ring, const float* __restrict__ x,
                                            int s, int tid, int bx)
{
    if (s < NSTAGES) {
        const int iu = s >> 1, h = s & 1;
        const int u  = bx + GRID * iu;           // < 1008
        const int bc = u / UNITS_PER_BC;
        const int U  = u - bc * UNITS_PER_BC;
        const int f0 = 64 * U - 1;               // first staged frame (may be -1)
        const float* xb = x + (size_t)bc * FRAMES * E_DIM + h * HALF;
        char* slot = ring + (s % 3) * SLOT_BYTES;
        uint32_t sbase = (uint32_t)__cvta_generic_to_shared(slot);
#pragma unroll
        for (int i = 0; i < 9; i++) {
            int c = tid + i * NTH;
            if (i < 8 || c < CHUNKS) {
                int f = f0 + (c >> 6);           // frame for this 16B chunk
                uint32_t sa = sbase + c * 16;
                if ((unsigned)f < FRAMES) {
                    cp16(sa, xb + (size_t)f * E_DIM + (c & 63) * 4);
                } else {
                    asm volatile("st.shared.v4.b32 [%0], {%1,%1,%1,%1};" :: "r"(sa), "r"(0));
                }
            }
        }
    }
    cp_commit();
}

__global__ __launch_bounds__(NTH)
void decoder_oadd_ring2(const float* __restrict__ x,
                        const float* __restrict__ wt,
                        float* __restrict__ out)
{
    extern __shared__ __align__(16) char smem[];
    float* wsm = (float*)smem;
    char*  ring = smem + W_BYTES;

    const int tid = threadIdx.x;
    const int bx  = blockIdx.x;

    // stage weights (4 float4 per thread)
#pragma unroll
    for (int i = 0; i < (16 * E_DIM) / (4 * NTH); i++) {
        int idx = (i * NTH + tid) * 4;
        *(float4*)(wsm + idx) = *(const float4*)(wt + idx);
    }

    // prologue: prefetch stages 0,1,2
    issue_stage(ring, x, 0, tid, bx);
    issue_stage(ring, x, 1, tid, bx);
    issue_stage(ring, x, 2, tid, bx);

    const int ks = tid & 7;            // lane bits 0-2: k slice within half
    const int rh = (tid >> 3) & 1;     // lane bit 3 : row half (rows rb..rb+3, +8)
    const int gl = (tid >> 4) & 1;     // lane bit 4 : group within warp
    const int kh = (tid >> 8) & 1;     // warp-level : which K half
    const int gloc = ((tid >> 5) & 7) * 2 + gl;   // group 0..15 within unit
    const int rb = rh * 4;

    const float* wA0 = wsm + rb * E_DIM + kh * HALF + ks * 4;  // rows rb..rb+3
    const float* wB0 = wA0 + 8 * E_DIM;                         // rows rb+8..

#pragma unroll 1
    for (int iu = 0; iu < UNITS_PER_BLOCK; iu++) {
        const int u  = bx + GRID * iu;
        const int bc = u / UNITS_PER_BC;
        const int U  = u - bc * UNITS_PER_BC;
        const int p0 = 32 * U + 2 * gloc;        // this thread's first pair

        ull a0[4], a1[4], b0[4], b1[4];
#pragma unroll
        for (int j = 0; j < 4; j++) { a0[j]=0; a1[j]=0; b0[j]=0; b1[j]=0; }

        cp_wait1();                 // stages 2iu and 2iu+1 resident
        __syncthreads();

        // rows 4*gloc .. 4*gloc+4 of this thread's k-half slot hold frames
        // 2p0-1 .. 2p0+3 (zeros at sequence edges)
        const char* xg = ring + ((2 * iu + kh) % 3) * SLOT_BYTES
                       + (4 * gloc) * 1024 + ks * 16;

#pragma unroll
        for (int i = 0; i < 8; i++) {
            const int xo = i * 128;
            ulonglong2 xm1 = *(const ulonglong2*)(xg +            xo);
            ulonglong2 x0  = *(const ulonglong2*)(xg + 1 * 1024 + xo);
            ulonglong2 x1  = *(const ulonglong2*)(xg + 2 * 1024 + xo);
            ulonglong2 x2  = *(const ulonglong2*)(xg + 3 * 1024 + xo);
            ulonglong2 x3  = *(const ulonglong2*)(xg + 4 * 1024 + xo);
#pragma unroll
            for (int j = 0; j < 4; j++) {
                ulonglong2 wl = *(const ulonglong2*)(wA0 + j * E_DIM + i * 32);
                ulonglong2 wh = *(const ulonglong2*)(wB0 + j * E_DIM + i * 32);
                ffma2(a0[j], x0.x,  wl.x);  ffma2(a0[j], x0.y,  wl.y);
                ffma2(a0[j], xm1.x, wh.x);  ffma2(a0[j], xm1.y, wh.y);
                ffma2(a1[j], x1.x,  wl.x);  ffma2(a1[j], x1.y,  wl.y);
                ffma2(a1[j], x0.x,  wh.x);  ffma2(a1[j], x0.y,  wh.y);
                ffma2(b0[j], x2.x,  wl.x);  ffma2(b0[j], x2.y,  wl.y);
                ffma2(b0[j], x1.x,  wh.x);  ffma2(b0[j], x1.y,  wh.y);
                ffma2(b1[j], x3.x,  wl.x);  ffma2(b1[j], x3.y,  wl.y);
                ffma2(b1[j], x2.x,  wh.x);  ffma2(b1[j], x2.y,  wh.y);
            }
        }

        // packed horizontal add + reduce over the 8 ks lanes (lane bits 0-2)
        float sv[16];
#pragma unroll
        for (int j = 0; j < 4; j++) {
            sv[j]      = flo(a0[j]) + fhi(a0[j]);
            sv[4 + j]  = flo(a1[j]) + fhi(a1[j]);
            sv[8 + j]  = flo(b0[j]) + fhi(b0[j]);
            sv[12 + j] = flo(b1[j]) + fhi(b1[j]);
        }
#pragma unroll
        for (int m = 1; m <= 4; m <<= 1)
#pragma unroll
            for (int j = 0; j < 16; j++)
                sv[j] += __shfl_xor_sync(0xffffffffu, sv[j], m);

        __syncthreads();    // both slots fully consumed by all warps

        // cross-kh combine through the consumed h=1 slot (2 KB scratch)
        float* scr = (float*)(ring + ((2 * iu + 1) % 3) * SLOT_BYTES);
        if (kh == 1 && ks == 0) {
            float* d = scr + (gloc * 2 + rh) * 16;
#pragma unroll
            for (int j = 0; j < 16; j++) d[j] = sv[j];
        }
        __syncthreads();

        if (kh == 0 && ks == 0 && p0 < PAIRS) {
            const float* d = scr + (gloc * 2 + rh) * 16;
            float* o = out + (size_t)bc * OUT_T + (size_t)p0 * 16 + rb;
            *(float4*)(o)      = make_float4(sv[0]+d[0],   sv[1]+d[1],   sv[2]+d[2],   sv[3]+d[3]);
            *(float4*)(o + 8)  = make_float4(sv[4]+d[4],   sv[5]+d[5],   sv[6]+d[6],   sv[7]+d[7]);
            *(float4*)(o + 16) = make_float4(sv[8]+d[8],   sv[9]+d[9],   sv[10]+d[10], sv[11]+d[11]);
            *(float4*)(o + 24) = make_float4(sv[12]+d[12], sv[13]+d[13], sv[14]+d[14], sv[15]+d[15]);
        }
        __syncthreads();    // scratch reads done before the slot is refilled

        issue_stage(ring, x, 2 * iu + 3, tid, bx);
        issue_stage(ring, x, 2 * iu + 4, tid, bx);
    }
}

extern "C" void kernel_launch(void* const* d_in, const int* in_sizes, int n_in,
                              void* d_out, int out_size)
{
    const float *x, *wt;
    if (in_sizes[0] > in_sizes[1]) { x = (const float*)d_in[0]; wt = (const float*)d_in[1]; }
    else                           { x = (const float*)d_in[1]; wt = (const float*)d_in[0]; }

    cudaFuncSetAttribute(decoder_oadd_ring2,
                         cudaFuncAttributeMaxDynamicSharedMemorySize, SMEM_TOTAL);

    decoder_oadd_ring2<<<GRID, NTH, SMEM_TOTAL>>>(x, wt, (float*)d_out);
}

// round 10
// speedup vs baseline: 1.3656x; 1.3656x over previous
#include <cuda_runtime.h>
#include <cstdint>

// Custom_Decoder fused GEMM + overlap_add; cp.async ring, 512 threads,
// quarter-K stages (R5 schedule: 3 slots, wait_group 2, consume->sync->refill).
//
// out[bc,16p+r]   = x[2p].wt[r]   + x[2p-1].wt[8+r]
// out[bc,16p+8+r] = x[2p+1].wt[r] + x[2p]  .wt[8+r]
//
// 128 blocks x 4 units; unit = 64 pairs (128 frames) of one bc (32 units/bc,
// last unit partially used; OOB frames zero-filled, stores predicated).
// Stage = (unit, k-quarter): slot = 129 rows x 512 B.

#define E_DIM 512
#define QUART 128
#define FRAMES 3999
#define PAIRS 2000
#define OUT_T 32000
#define GRID 128
#define UNITS_PER_BLOCK 4
#define NSTAGES (4*UNITS_PER_BLOCK)    // 16
#define NTH 512
#define SLOT_BYTES (129*512)           // 66048
#define W_BYTES (16*E_DIM*4)           // 32768
#define SMEM_TOTAL (W_BYTES + 3*SLOT_BYTES)   // 230912 <= 232448 optin
#define CHUNKS (SLOT_BYTES/16)         // 4128

typedef unsigned long long ull;

__device__ __forceinline__ void ffma2(ull &d, ull a, ull b) {
    asm("fma.rn.f32x2 %0, %1, %2, %0;" : "+l"(d) : "l"(a), "l"(b));
}
__device__ __forceinline__ float flo(ull v){ return __uint_as_float((unsigned)(v & 0xffffffffu)); }
__device__ __forceinline__ float fhi(ull v){ return __uint_as_float((unsigned)(v >> 32)); }

__device__ __forceinline__ void cp16(uint32_t sa, const void* g) {
    asm volatile("cp.async.cg.shared.global [%0], [%1], 16;" :: "r"(sa), "l"(g));
}
__device__ __forceinline__ void cp_commit() { asm volatile("cp.async.commit_group;"); }
__device__ __forceinline__ void cp_wait2()  { asm volatile("cp.async.wait_group 2;"); }

// stage s: unit iu = s/4, quarter q = s&3. Always commits (empty groups past
// the end keep wait_group(2) bookkeeping uniform).
__device__ __forceinline__ void issue_stage(char* ring, const float* __restrict__ x,
                                            int s, int tid, int bx)
{
    if (s < NSTAGES) {
        const int u  = bx * UNITS_PER_BLOCK + (s >> 2);   // < 512
        const int q  = s & 3;
        const int bc = u >> 5;               // 32 units per bc
        const int U  = u & 31;
        const int f0 = 128 * U - 1;          // first staged frame (may be <0 / >=FRAMES)
        const float* xb = x + (size_t)bc * FRAMES * E_DIM + q * QUART;
        char* slot = ring + (s % 3) * SLOT_BYTES;
        uint32_t sbase = (uint32_t)__cvta_generic_to_shared(slot);
#pragma unroll
        for (int i = 0; i < 9; i++) {
            int c = tid + i * NTH;
            if (i < 8 || c < CHUNKS) {
                int f = f0 + (c >> 5);       // 32 chunks of 16B per 512B row
                uint32_t sa = sbase + c * 16;
                if ((unsigned)f < FRAMES) {
                    cp16(sa, xb + (size_t)f * E_DIM + (c & 31) * 4);
                } else {
                    asm volatile("st.shared.v4.b32 [%0], {%1,%1,%1,%1};" :: "r"(sa), "r"(0));
                }
            }
        }
    }
    cp_commit();
}

__global__ __launch_bounds__(NTH)
void decoder_oadd_q(const float* __restrict__ x,
                    const float* __restrict__ wt,
                    float* __restrict__ out)
{
    extern __shared__ __align__(16) char smem[];
    float* wsm = (float*)smem;
    char*  ring = smem + W_BYTES;

    const int tid = threadIdx.x;
    const int bx  = blockIdx.x;

    // stage weights (4 float4 per thread)
#pragma unroll
    for (int i = 0; i < (16 * E_DIM) / (4 * NTH); i++) {
        int idx = (i * NTH + tid) * 4;
        *(float4*)(wsm + idx) = *(const float4*)(wt + idx);
    }

    // prologue: prefetch stages 0,1,2
    issue_stage(ring, x, 0, tid, bx);
    issue_stage(ring, x, 1, tid, bx);
    issue_stage(ring, x, 2, tid, bx);

    const int lane = tid & 31;
    const int wid  = tid >> 5;          // 0..15
    const int ks   = lane & 7;          // k slice within quarter (4*ks + 32*i)
    const int rh   = (lane >> 3) & 1;   // row half (rows rb..rb+3, +8)
    const int gl   = lane >> 4;         // group within warp (weight addrs shared)
    const int gloc = wid * 2 + gl;      // group 0..31 within unit
    const int rb   = rh * 4;

#pragma unroll 1
    for (int iu = 0; iu < UNITS_PER_BLOCK; iu++) {
        const int u  = bx * UNITS_PER_BLOCK + iu;
        const int bc = u >> 5;
        const int U  = u & 31;
        const int p0 = 64 * U + 2 * gloc;        // this thread's first pair

        ull a0[4], a1[4], b0[4], b1[4];
#pragma unroll
        for (int j = 0; j < 4; j++) { a0[j]=0; a1[j]=0; b0[j]=0; b1[j]=0; }

#pragma unroll 1
        for (int q = 0; q < 4; q++) {
            const int s = 4 * iu + q;
            cp_wait2();
            __syncthreads();

            // rows 4*gloc .. 4*gloc+4 hold frames 2p0-1 .. 2p0+3 (zeros OOB)
            const char* xg = ring + (s % 3) * SLOT_BYTES + (4 * gloc) * 512 + ks * 16;
            const float* wA = wsm + rb * E_DIM + q * QUART + ks * 4;   // rows rb..rb+3
            const float* wB = wA + 8 * E_DIM;                          // rows rb+8..

#pragma unroll
            for (int i = 0; i < 4; i++) {
                const int xo = i * 128;          // 32 floats per granule step
                ulonglong2 xm1 = *(const ulonglong2*)(xg +           xo);
                ulonglong2 x0  = *(const ulonglong2*)(xg + 1 * 512 + xo);
                ulonglong2 x1  = *(const ulonglong2*)(xg + 2 * 512 + xo);
                ulonglong2 x2  = *(const ulonglong2*)(xg + 3 * 512 + xo);
                ulonglong2 x3  = *(const ulonglong2*)(xg + 4 * 512 + xo);
#pragma unroll
                for (int j = 0; j < 4; j++) {
                    ulonglong2 wl = *(const ulonglong2*)(wA + j * E_DIM + i * 32);
                    ulonglong2 wh = *(const ulonglong2*)(wB + j * E_DIM + i * 32);
                    ffma2(a0[j], x0.x,  wl.x);  ffma2(a0[j], x0.y,  wl.y);
                    ffma2(a0[j], xm1.x, wh.x);  ffma2(a0[j], xm1.y, wh.y);
                    ffma2(a1[j], x1.x,  wl.x);  ffma2(a1[j], x1.y,  wl.y);
                    ffma2(a1[j], x0.x,  wh.x);  ffma2(a1[j], x0.y,  wh.y);
                    ffma2(b0[j], x2.x,  wl.x);  ffma2(b0[j], x2.y,  wl.y);
                    ffma2(b0[j], x1.x,  wh.x);  ffma2(b0[j], x1.y,  wh.y);
                    ffma2(b1[j], x3.x,  wl.x);  ffma2(b1[j], x3.y,  wl.y);
                    ffma2(b1[j], x2.x,  wh.x);  ffma2(b1[j], x2.y,  wh.y);
                }
            }
            __syncthreads();                 // slot fully consumed by all warps
            issue_stage(ring, x, s + 3, tid, bx);   // refill (or empty commit)
        }

        // epilogue: packed horizontal add, reduce over 8 ks lanes, store
        float sv[16];
#pragma unroll
        for (int j = 0; j < 4; j++) {
            sv[j]      = flo(a0[j]) + fhi(a0[j]);
            sv[4 + j]  = flo(a1[j]) + fhi(a1[j]);
            sv[8 + j]  = flo(b0[j]) + fhi(b0[j]);
            sv[12 + j] = flo(b1[j]) + fhi(b1[j]);
        }
#pragma unroll
        for (int m = 1; m <= 4; m <<= 1)
#pragma unroll
            for (int j = 0; j < 16; j++)
                sv[j] += __shfl_xor_sync(0xffffffffu, sv[j], m);

        if (ks == 0 && p0 < PAIRS) {
            float* o = out + (size_t)bc * OUT_T + (size_t)p0 * 16 + rb;
            *(float4*)(o)      = make_float4(sv[0],  sv[1],  sv[2],  sv[3]);
            *(float4*)(o + 8)  = make_float4(sv[4],  sv[5],  sv[6],  sv[7]);
            *(float4*)(o + 16) = make_float4(sv[8],  sv[9],  sv[10], sv[11]);
            *(float4*)(o + 24) = make_float4(sv[12], sv[13], sv[14], sv[15]);
        }
    }
}

extern "C" void kernel_launch(void* const* d_in, const int* in_sizes, int n_in,
                              void* d_out, int out_size)
{
    const float *x, *wt;
    if (in_sizes[0] > in_sizes[1]) { x = (const float*)d_in[0]; wt = (const float*)d_in[1]; }
    else                           { x = (const float*)d_in[1]; wt = (const float*)d_in[0]; }

    cudaFuncSetAttribute(decoder_oadd_q,
                         cudaFuncAttributeMaxDynamicSharedMemorySize, SMEM_TOTAL);

    decoder_oadd_q<<<GRID, NTH, SMEM_TOTAL>>>(x, wt, (float*)d_out);
}

// round 12
// speedup vs baseline: 1.4515x; 1.0629x over previous
#include <cuda_runtime.h>
#include <cstdint>

// Custom_Decoder fused GEMM + overlap_add; cp.async 4-slot ring,
// ONE __syncthreads per stage, 2 CTAs/SM (decoupled pipelines).
//
// out[bc,16p+r]   = x[2p].wt[r]   + x[2p-1].wt[8+r]
// out[bc,16p+8+r] = x[2p+1].wt[r] + x[2p]  .wt[8+r]
//
// 252 blocks x 4 units = 1008 units = 16 bc x 63; unit = 32 pairs (64 frames).
// Stage = K-eighth of a unit: slot = 65 rows x 256 B (frames 64U-1..64U+63,
// OOB rows zero-filled).  4 slots, wait_group 2, refill-before-compute.

#define E_DIM 512
#define FRAMES 3999
#define PAIRS 2000
#define OUT_T 32000
#define GRID 252
#define UPB 4
#define NSTAGES (UPB*8)            // 32
#define NTH 256
#define SLOT_BYTES (65*256)        // 16640
#define W_BYTES (16*E_DIM*4)       // 32768
#define SMEM_TOTAL (W_BYTES + 4*SLOT_BYTES)   // 99328 -> 2 CTAs/SM
#define CHUNKS (SLOT_BYTES/16)     // 1040

typedef unsigned long long ull;

__device__ __forceinline__ void ffma2(ull &d, ull a, ull b) {
    asm("fma.rn.f32x2 %0, %1, %2, %0;" : "+l"(d) : "l"(a), "l"(b));
}
__device__ __forceinline__ float flo(ull v){ return __uint_as_float((unsigned)(v & 0xffffffffu)); }
__device__ __forceinline__ float fhi(ull v){ return __uint_as_float((unsigned)(v >> 32)); }

__device__ __forceinline__ void cp16(uint32_t sa, const void* g) {
    asm volatile("cp.async.cg.shared.global [%0], [%1], 16;" :: "r"(sa), "l"(g));
}
__device__ __forceinline__ void cp_commit() { asm volatile("cp.async.commit_group;"); }
__device__ __forceinline__ void cp_wait2()  { asm volatile("cp.async.wait_group 2;"); }

// stage s: unit iu = s/8, k-eighth q = s&7.  Always commits.
__device__ __forceinline__ void issue_stage(uint32_t ringb, const float* __restrict__ x,
                                            int s, int tid, int bx)
{
    if (s < NSTAGES) {
        const int u  = bx * UPB + (s >> 3);      // < 1008
        const int q  = s & 7;
        const int bc = u / 63;
        const int U  = u - bc * 63;
        const int f0 = 64 * U - 1;               // row 0 frame (may be -1 / OOB)
        const float* xb = x + (size_t)bc * FRAMES * E_DIM + q * 64;
        uint32_t slot = ringb + (uint32_t)(s & 3) * SLOT_BYTES;
#pragma unroll
        for (int i = 0; i < 5; i++) {
            int c = tid + i * NTH;
            if (i < 4 || c < CHUNKS) {
                int f = f0 + (c >> 4);           // 16 chunks of 16B per 256B row
                uint32_t sa = slot + c * 16;
                if ((unsigned)f < FRAMES) {
                    cp16(sa, xb + (size_t)f * E_DIM + (c & 15) * 4);
                } else {
                    asm volatile("st.shared.v4.b32 [%0], {%1,%1,%1,%1};" :: "r"(sa), "r"(0));
                }
            }
        }
    }
    cp_commit();
}

__global__ __launch_bounds__(NTH)
void decoder_oadd_r9(const float* __restrict__ x,
                     const float* __restrict__ wt,
                     float* __restrict__ out)
{
    extern __shared__ __align__(16) char smem[];
    float* wsm = (float*)smem;
    uint32_t ringb = (uint32_t)__cvta_generic_to_shared(smem + W_BYTES);
    char* ring = smem + W_BYTES;

    const int tid = threadIdx.x;
    const int bx  = blockIdx.x;

    // stage weights (8 float4 per thread)
#pragma unroll
    for (int i = 0; i < (16 * E_DIM) / (4 * NTH); i++) {
        int idx = (i * NTH + tid) * 4;
        *(float4*)(wsm + idx) = *(const float4*)(wt + idx);
    }

    // prologue: prefetch stages 0,1,2
    issue_stage(ringb, x, 0, tid, bx);
    issue_stage(ringb, x, 1, tid, bx);
    issue_stage(ringb, x, 2, tid, bx);

    const int lane = tid & 31;
    const int ks   = lane & 7;          // k slice: floats 4ks + 32i of the eighth
    const int rh   = (lane >> 3) & 1;   // row half (rows rb..rb+3, +8)
    const int gl   = lane >> 4;         // group within warp (weight addrs shared)
    const int gloc = (tid >> 5) * 2 + gl;   // group 0..15 within unit
    const int rb   = rh * 4;

#pragma unroll 1
    for (int iu = 0; iu < UPB; iu++) {
        const int u  = bx * UPB + iu;
        const int bc = u / 63;
        const int U  = u - bc * 63;
        const int p0 = 32 * U + 2 * gloc;        // thread's first pair

        ull a0[4], a1[4], b0[4], b1[4];
#pragma unroll
        for (int j = 0; j < 4; j++) { a0[j]=0; a1[j]=0; b0[j]=0; b1[j]=0; }

#pragma unroll 1
        for (int q = 0; q < 8; q++) {
            const int s = iu * 8 + q;
            cp_wait2();                 // fill(s) drained (own groups)
            __syncthreads();            // publish fill(s); proves s-1 consumed
            issue_stage(ringb, x, s + 3, tid, bx);   // into slot consumed at s-1

            // rows 4*gloc..4*gloc+4 hold frames 2p0-1..2p0+3 (zeros OOB)
            const char* xg = ring + (s & 3) * SLOT_BYTES + (4 * gloc) * 256 + ks * 16;
            const float* wA = wsm + rb * E_DIM + q * 64 + ks * 4;   // rows rb..rb+3
            const float* wB = wA + 8 * E_DIM;                       // rows rb+8..

#pragma unroll
            for (int i = 0; i < 2; i++) {
                const int xo = i * 128;
                ulonglong2 xm1 = *(const ulonglong2*)(xg +           xo);
                ulonglong2 x0  = *(const ulonglong2*)(xg + 1 * 256 + xo);
                ulonglong2 x1  = *(const ulonglong2*)(xg + 2 * 256 + xo);
                ulonglong2 x2  = *(const ulonglong2*)(xg + 3 * 256 + xo);
                ulonglong2 x3  = *(const ulonglong2*)(xg + 4 * 256 + xo);
#pragma unroll
                for (int j = 0; j < 4; j++) {
                    ulonglong2 wl = *(const ulonglong2*)(wA + j * E_DIM + i * 32);
                    ulonglong2 wh = *(const ulonglong2*)(wB + j * E_DIM + i * 32);
                    ffma2(a0[j], x0.x,  wl.x);  ffma2(a0[j], x0.y,  wl.y);
                    ffma2(a0[j], xm1.x, wh.x);  ffma2(a0[j], xm1.y, wh.y);
                    ffma2(a1[j], x1.x,  wl.x);  ffma2(a1[j], x1.y,  wl.y);
                    ffma2(a1[j], x0.x,  wh.x);  ffma2(a1[j], x0.y,  wh.y);
                    ffma2(b0[j], x2.x,  wl.x);  ffma2(b0[j], x2.y,  wl.y);
                    ffma2(b0[j], x1.x,  wh.x);  ffma2(b0[j], x1.y,  wh.y);
                    ffma2(b1[j], x3.x,  wl.x);  ffma2(b1[j], x3.y,  wl.y);
                    ffma2(b1[j], x2.x,  wh.x);  ffma2(b1[j], x2.y,  wh.y);
                }
            }
        }

        // epilogue: packed horizontal add, reduce over 8 ks lanes, store
        float sv[16];
#pragma unroll
        for (int j = 0; j < 4; j++) {
            sv[j]      = flo(a0[j]) + fhi(a0[j]);
            sv[4 + j]  = flo(a1[j]) + fhi(a1[j]);
            sv[8 + j]  = flo(b0[j]) + fhi(b0[j]);
            sv[12 + j] = flo(b1[j]) + fhi(b1[j]);
        }
#pragma unroll
        for (int m = 1; m <= 4; m <<= 1)
#pragma unroll
            for (int j = 0; j < 16; j++)
                sv[j] += __shfl_xor_sync(0xffffffffu, sv[j], m);

        if (ks == 0 && p0 < PAIRS) {
            float* o = out + (size_t)bc * OUT_T + (size_t)p0 * 16 + rb;
            *(float4*)(o)      = make_float4(sv[0],  sv[1],  sv[2],  sv[3]);
            *(float4*)(o + 8)  = make_float4(sv[4],  sv[5],  sv[6],  sv[7]);
            *(float4*)(o + 16) = make_float4(sv[8],  sv[9],  sv[10], sv[11]);
            *(float4*)(o + 24) = make_float4(sv[12], sv[13], sv[14], sv[15]);
        }
    }
}

extern "C" void kernel_launch(void* const* d_in, const int* in_sizes, int n_in,
                              void* d_out, int out_size)
{
    const float *x, *wt;
    if (in_sizes[0] > in_sizes[1]) { x = (const float*)d_in[0]; wt = (const float*)d_in[1]; }
    else                           { x = (const float*)d_in[1]; wt = (const float*)d_in[0]; }

    cudaFuncSetAttribute(decoder_oadd_r9,
                         cudaFuncAttributeMaxDynamicSharedMemorySize, SMEM_TOTAL);

    decoder_oadd_r9<<<GRID, NTH, SMEM_TOTAL>>>(x, wt, (float*)d_out);
}